// round 17
// baseline (speedup 1.0000x reference)
#include <cuda_runtime.h>
#include <cuda_bf16.h>
#include <cstdint>

// CorrelationLayer via warp-level mma.sync (HMMA) Gram-band GEMM.
// D[m,q] = sum_c x1[m,c]*x2[q,c], m = 128 x1 pixels (8h x 16w tile),
// q = 96 x2 patch pixels per subtile (4 patch rows x 24 cols), K = 128 ch.
// bf16 hi/lo split, 3 products, fp32 accum -> rel err ~1e-5.
// Fragments staged in smem in mma-fragment order (1 LDS.128 per A frag).

#define CC 128
#define HH 128
#define WW 192
#define NTHREADS 256
#define SCALE 0.08838834764831845f   // 1/sqrt(128)

// smem map (56 KB):
//   A frags: [0, 32768)      2 planes x 8 mt x 4 ks x 32 lanes x 16 B
//   B frags: [32768, 57344)  2 planes x 12 nt x 4 ks x 32 lanes x 8 B
//   D stage: [0, 51200)      128 rows x 100 floats (aliases A/B after MMA)
#define A_PLANE 16384
#define B_BASE  32768
#define B_PLANE 12288

static __device__ __forceinline__ void mma_bf16(float c[4],
    uint32_t a0, uint32_t a1, uint32_t a2, uint32_t a3,
    uint32_t b0, uint32_t b1)
{
    asm("mma.sync.aligned.m16n8k16.row.col.f32.bf16.bf16.f32 "
        "{%0,%1,%2,%3}, {%4,%5,%6,%7}, {%8,%9}, {%0,%1,%2,%3};"
        : "+f"(c[0]), "+f"(c[1]), "+f"(c[2]), "+f"(c[3])
        : "r"(a0), "r"(a1), "r"(a2), "r"(a3), "r"(b0), "r"(b1));
}

static __device__ __forceinline__ void cvt2(float f0, float f1,
                                            uint32_t& hp, uint32_t& lp) {
    __nv_bfloat16 h0 = __float2bfloat16_rn(f0);
    __nv_bfloat16 h1 = __float2bfloat16_rn(f1);
    float r0 = f0 - __bfloat162float(h0);
    float r1 = f1 - __bfloat162float(h1);
    __nv_bfloat16 l0 = __float2bfloat16_rn(r0);
    __nv_bfloat16 l1 = __float2bfloat16_rn(r1);
    hp = (uint32_t)__bfloat16_as_ushort(h0) | ((uint32_t)__bfloat16_as_ushort(h1) << 16);
    lp = (uint32_t)__bfloat16_as_ushort(l0) | ((uint32_t)__bfloat16_as_ushort(l1) << 16);
}

__global__ __launch_bounds__(NTHREADS, 2)
void corr_mma(const float* __restrict__ x1,
              const float* __restrict__ x2,
              float* __restrict__ out)
{
    __shared__ __align__(16) char sm[57344];

    const int tid  = threadIdx.x;
    const int lane = tid & 31;
    const int wid  = tid >> 5;            // 0..7
    const int warp_m = wid >> 2;          // 0..1  (64 rows each)
    const int warp_n = wid & 3;           // 0..3  (24 cols each)

    const int blk = blockIdx.x;
    const int b   = blk / 192;
    const int rem = blk % 192;
    const int h0  = (rem / 12) * 8;
    const int w0  = (rem % 12) * 16;

    const size_t chw = (size_t)HH * WW;

    #pragma unroll 1
    for (int sub = 0; sub < 4; sub++) {
        float acc[4][3][4];
        #pragma unroll
        for (int i = 0; i < 4; i++)
            #pragma unroll
            for (int j = 0; j < 3; j++)
                #pragma unroll
                for (int r = 0; r < 4; r++) acc[i][j][r] = 0.0f;

        #pragma unroll 1
        for (int kc = 0; kc < 2; kc++) {
            // ---- A conversion: 128 px x 32 ch-pairs -> fragment layout ----
            #pragma unroll 1
            for (int u = tid; u < 4096; u += NTHREADS) {
                int px = u & 127;                 // m index: ph*16+pw
                int c2 = u >> 7;                  // 0..31
                int ph = px >> 4, pw = px & 15;
                int c  = kc * 64 + 2 * c2;
                const float* g = x1 + ((size_t)(b * CC + c) * HH + (h0 + ph)) * WW
                               + (w0 + pw);
                uint32_t hp, lp;
                cvt2(g[0], g[chw], hp, lp);
                int mt = px >> 4, r = px & 15;
                int ks = c2 >> 3, kk = c2 & 7, t = kk & 3;
                int reg = ((r >> 3) & 1) | ((kk >> 2) << 1);
                int ln  = (r & 7) * 4 + t;
                uint32_t off = (uint32_t)((((mt * 4 + ks) * 32 + ln) << 4) + (reg << 2));
                *(uint32_t*)(sm + off)           = hp;
                *(uint32_t*)(sm + A_PLANE + off) = lp;
            }
            // ---- B conversion: 96 patch px x 32 ch-pairs (OOB -> 0) ----
            #pragma unroll 1
            for (int u = tid; u < 3072; u += NTHREADS) {
                int n  = u % 96;                  // rh*24 + wq
                int c2 = u / 96;
                int rh = n / 24, wq = n % 24;
                int gh = h0 + sub * 4 + rh - 4;
                int gw = w0 + wq - 4;
                int c  = kc * 64 + 2 * c2;
                float f0 = 0.f, f1 = 0.f;
                if ((unsigned)gh < (unsigned)HH && (unsigned)gw < (unsigned)WW) {
                    const float* g = x2 + ((size_t)(b * CC + c) * HH + gh) * WW + gw;
                    f0 = g[0]; f1 = g[chw];
                }
                uint32_t hp, lp;
                cvt2(f0, f1, hp, lp);
                int nt = n >> 3, nn = n & 7;
                int ks = c2 >> 3, kk = c2 & 7, t = kk & 3;
                int reg = kk >> 2;
                int ln  = nn * 4 + t;
                uint32_t off = (uint32_t)(B_BASE + (((nt * 4 + ks) * 32 + ln) << 3)
                                          + (reg << 2));
                *(uint32_t*)(sm + off)           = hp;
                *(uint32_t*)(sm + B_PLANE + off) = lp;
            }
            __syncthreads();

            // ---- MMA: warp tile 64x24, 3 products ----
            #pragma unroll
            for (int ks = 0; ks < 4; ks++) {
                uint4 Ah[4], Al[4];
                #pragma unroll
                for (int i = 0; i < 4; i++) {
                    uint32_t off = (uint32_t)(((((warp_m * 4 + i) * 4 + ks) * 32
                                                + lane) << 4));
                    Ah[i] = *(const uint4*)(sm + off);
                    Al[i] = *(const uint4*)(sm + A_PLANE + off);
                }
                uint2 Bh[3], Bl[3];
                #pragma unroll
                for (int j = 0; j < 3; j++) {
                    uint32_t off = (uint32_t)(B_BASE + ((((warp_n * 3 + j) * 4 + ks) * 32
                                                         + lane) << 3));
                    Bh[j] = *(const uint2*)(sm + off);
                    Bl[j] = *(const uint2*)(sm + B_PLANE + off);
                }
                #pragma unroll
                for (int i = 0; i < 4; i++)
                    #pragma unroll
                    for (int j = 0; j < 3; j++) {
                        mma_bf16(acc[i][j], Ah[i].x, Ah[i].y, Ah[i].z, Ah[i].w,
                                 Bh[j].x, Bh[j].y);
                        mma_bf16(acc[i][j], Ah[i].x, Ah[i].y, Ah[i].z, Ah[i].w,
                                 Bl[j].x, Bl[j].y);
                        mma_bf16(acc[i][j], Al[i].x, Al[i].y, Al[i].z, Al[i].w,
                                 Bh[j].x, Bh[j].y);
                    }
            }
            __syncthreads();   // frags consumed; safe to overwrite (next kc / D stage)
        }

        // ---- stage D (128 x 96, stride 100) ----
        {
            int g = lane >> 2, t = lane & 3;
            #pragma unroll
            for (int i = 0; i < 4; i++) {
                int m0 = warp_m * 64 + i * 16 + g;
                #pragma unroll
                for (int j = 0; j < 3; j++) {
                    int q = warp_n * 24 + j * 8 + 2 * t;
                    *(float2*)(sm + ((m0 * 100 + q) << 2)) =
                        make_float2(acc[i][j][0], acc[i][j][1]);
                    *(float2*)(sm + (((m0 + 8) * 100 + q) << 2)) =
                        make_float2(acc[i][j][2], acc[i][j][3]);
                }
            }
        }
        __syncthreads();

        // ---- band extraction for this subtile ----
        if (tid < 144) {
            int di  = tid / 16;               // 0..8
            int rst = tid & 15;
            int ph  = rst >> 1;               // 0..7
            int pw8 = rst & 1;                // 0..1 (8 px each)
            int rh  = ph + di - sub * 4;
            if (rh >= 0 && rh < 4) {
                const float* D = (const float*)sm;
                #pragma unroll
                for (int dj = 0; dj < 9; dj++) {
                    int d = di * 9 + dj;
                    if (d == 40) continue;    // (0,0) displacement
                    int dc = d - (d > 40 ? 1 : 0);
                    float v[8];
                    #pragma unroll
                    for (int p = 0; p < 8; p++) {
                        int pw = pw8 * 8 + p;
                        v[p] = D[(ph * 16 + pw) * 100 + rh * 24 + pw + dj] * SCALE;
                    }
                    float* dst = &out[(((size_t)(b * 80 + dc) * HH + h0 + ph) * WW)
                                      + w0 + pw8 * 8];
                    *(float4*)dst       = make_float4(v[0], v[1], v[2], v[3]);
                    *(float4*)(dst + 4) = make_float4(v[4], v[5], v[6], v[7]);
                }
            }
        }
        __syncthreads();
    }
}

extern "C" void kernel_launch(void* const* d_in, const int* in_sizes, int n_in,
                              void* d_out, int out_size)
{
    const float* x1 = (const float*)d_in[0];
    const float* x2 = (const float*)d_in[1];
    float* out = (float*)d_out;

    corr_mma<<<8 * 16 * 12, NTHREADS>>>(x1, x2, out);   // 1536 CTAs
}